// round 11
// baseline (speedup 1.0000x reference)
#include <cuda_runtime.h>
#include <cstdint>

#define NROW     256
#define S_STEPS  4001
#define M_STEPS  4000
#define NCHUNK   148
#define CLEN     28
#define GP_SIZE  33152
#define CODE_UP   300
#define CODE_NONE 301
#define RINF     (1<<20)
#define NTHR     512

// ---- device scratch (zero-init at load; no allocations) ----
__device__ __align__(16) float g_Gp[GP_SIZE];   // packed G(i,c): row i at off=i*(i+3)/2, idx off+1+c
__device__ int   g_sum_r[NCHUNK * NROW];        // per-chunk transform: forced value (RINF = pass)
__device__ int   g_sum_K[NCHUNK];               // per-chunk transform: min-clamp
__device__ unsigned          g_count;           // barrier arrivals (self-resetting)
__device__ volatile unsigned g_gen;             // barrier generation (monotonic across replays)

__device__ __forceinline__ float xval(int i) {
    if (i >= 255) return 1.0f;
    if (i <= 0)   return 0.0f;
    return (float)i * (1.0f / 255.0f);
}

__device__ __forceinline__ float hnorm(const float* __restrict__ hd, int s) {
    return (s == 0) ? 1.0f : (hd[s - 1] + 1.0f) * 0.5f;
}

// classify step s: up (h>p), down (h<p, code=jmax), or none
__device__ __forceinline__ void make_step(const float* __restrict__ hd, int s,
                                          float& h, int& code) {
    h = hnorm(hd, s);
    int pi = (s == 0) ? (S_STEPS - 1) : (s - 1);
    float p = hnorm(hd, pi);
    if (h > p) {
        code = CODE_UP;
    } else if (h < p) {
        int jm = (int)(h * 255.0f);
        if (jm > 255) jm = 255;
        if (jm < 0)   jm = 0;
        while (jm < 255 && xval(jm + 1) <= h) ++jm;   // exact float semantics
        while (jm >= 0 && xval(jm) > h)      --jm;
        code = jm;                                    // jmax in [-1, 255]
    } else {
        code = CODE_NONE;
    }
}

// jax.nn.softplus = max(x,0) + log1p(exp(-|x|))
__device__ __forceinline__ float softplus_f(float x) {
    return fmaxf(x, 0.0f) + log1pf(expf(-fabsf(x)));
}

// transform compose: t_out = t2 ∘ t1 (t1 applied first)
__device__ __forceinline__ void comp(int r1, int K1, int r2, int K2, int& r, int& K) {
    r = (r2 != RINF) ? r2 : ((r1 != RINF) ? min(r1, K2) : RINF);
    K = min(K1, K2);
}

// software grid barrier — safe: 148 CTAs, 1/SM, all resident in one wave
__device__ __forceinline__ void grid_barrier() {
    __syncthreads();
    if (threadIdx.x == 0) {
        __threadfence();                       // release phase-A writes
        unsigned start = g_gen;                // read BEFORE arriving
        unsigned old = atomicAdd(&g_count, 1u);
        if (old == NCHUNK - 1) {
            g_count = 0;                       // reset for next graph replay
            __threadfence();
            atomicAdd((unsigned*)&g_gen, 1u);
        } else {
            while (g_gen == start) { }         // busy spin: fastest wakeup
        }
        __threadfence();                       // acquire
    }
    __syncthreads();
}

__global__ void __launch_bounds__(NTHR, 1)
kFused(const float* __restrict__ raw, const float* __restrict__ hd,
       float* __restrict__ out) {
    int k = blockIdx.x, tid = threadIdx.x;
    int half = tid >> 8;
    int t8   = tid & 255;
    int lnl  = t8 & 31;
    int wl   = t8 >> 5;
    int w    = tid >> 5;
    int ln   = tid & 31;

    __shared__ float sh[CLEN];
    __shared__ int   sc[CLEN];
    __shared__ float wtot[16];
    __shared__ float awt[8];                 // partial sums for 'a'
    __shared__ int   sR[NROW], sKm[NROW];    // upper half's compose transform
    __shared__ int   sC[NROW];               // combined entry state
    __shared__ float mat[CLEN * NROW];

    // ---- step descriptors for this block's chunk ----
    if (tid < CLEN) {
        int s = k * CLEN + tid;
        float h = 0.0f; int code = CODE_NONE;
        if (s < S_STEPS) make_step(hd, s, h, code);
        sh[tid] = h; sc[tid] = code;
    }

    // ---- phase A1: both G rows concurrently (one per 256-thread half) ----
    {
        int i = k + half * NCHUNK;
        bool valid = (i < NROW);
        float v = 0.0f;
        if (valid && t8 <= i) v = softplus_f(__ldg(raw + i * (i + 1) / 2 + t8));

        float s = v;
        #pragma unroll
        for (int o = 1; o < 32; o <<= 1) {
            float t = __shfl_up_sync(0xffffffffu, s, o);
            if (lnl >= o) s += t;
        }
        if (lnl == 31) wtot[half * 8 + wl] = s;
        __syncthreads();
        if (wl == 0) {
            float t = (lnl < 8) ? wtot[half * 8 + lnl] : 0.0f;
            #pragma unroll
            for (int o = 1; o < 8; o <<= 1) {
                float u = __shfl_up_sync(0xffffffffu, t, o);
                if (lnl >= o) t += u;
            }
            if (lnl < 8) wtot[half * 8 + lnl] = t;
        }
        __syncthreads();
        float pre = s + ((wl > 0) ? wtot[half * 8 + wl - 1] : 0.0f);
        float R = wtot[half * 8 + 7];

        if (valid) {
            int off = i * (i + 3) / 2;
            if (t8 <= i) g_Gp[off + 1 + t8] = 2.0f * pre - R;
            if (t8 == 0) g_Gp[off] = -R;
        }
    }

    // ---- phase A2: chunk summary (lower half; sh/sc covered by A1 syncs) ----
    if (half == 0) {
        float xi = xval(t8);
        int r = RINF, K = RINF;
        #pragma unroll
        for (int l = 0; l < CLEN; l++) {
            int cd = sc[l];
            if (cd == CODE_UP) {
                if (xi < sh[l]) r = t8;
            } else if (cd != CODE_NONE) {
                if (r != RINF) r = min(r, cd);
                K = min(K, cd);
            }
        }
        g_sum_r[k * NROW + t8] = r;
        if (t8 == 0) g_sum_K[k] = K;
    }

    // ---- grid barrier: all G rows + summaries visible ----
    grid_barrier();

    // ---- compose: lower half [0,kmid), upper half [kmid,k); each thread runs
    //      4 independent sub-chains so loads stream ahead of the ALU chains ----
    {
        int kmid = k >> 1;
        int lo = half ? kmid : 0;
        int hi = half ? k : kmid;
        int n  = hi - lo;
        int q4 = n >> 2;

        int R0 = RINF, K0 = RINF, R1 = RINF, K1 = RINF;
        int R2 = RINF, K2 = RINF, R3 = RINF, K3 = RINF;
        const int* rr = g_sum_r + t8;

        for (int j = 0; j < q4; j++) {
            int i0 = lo + j;
            int i1 = lo + q4 + j;
            int i2 = lo + 2 * q4 + j;
            int i3 = lo + 3 * q4 + j;
            int a0 = rr[i0 * NROW], b0 = __ldg(g_sum_K + i0);
            int a1 = rr[i1 * NROW], b1 = __ldg(g_sum_K + i1);
            int a2 = rr[i2 * NROW], b2 = __ldg(g_sum_K + i2);
            int a3 = rr[i3 * NROW], b3 = __ldg(g_sum_K + i3);
            comp(R0, K0, a0, b0, R0, K0);
            comp(R1, K1, a1, b1, R1, K1);
            comp(R2, K2, a2, b2, R2, K2);
            comp(R3, K3, a3, b3, R3, K3);
        }
        for (int idx = lo + 4 * q4; idx < hi; idx++) {
            comp(R3, K3, rr[idx * NROW], __ldg(g_sum_K + idx), R3, K3);
        }
        // combine sub-chains in ascending order
        int Ra, Ka, Rb, Kb, Rf, Kf;
        comp(R0, K0, R1, K1, Ra, Ka);
        comp(R2, K2, R3, K3, Rb, Kb);
        comp(Ra, Ka, Rb, Kb, Rf, Kf);

        if (half == 1) { sR[t8] = Rf; sKm[t8] = Kf; }
        __syncthreads();
        if (half == 0) {
            int c = -1;
            c = (Rf != RINF) ? Rf : min(c, Kf);     // apply [0,kmid)
            int Rh = sR[t8], Kh = sKm[t8];
            c = (Rh != RINF) ? Rh : min(c, Kh);     // apply [kmid,k)
            sC[t8] = c;
        }
        __syncthreads();
    }

    // ---- phase C: precompute c-sequence (ALU-only), gather G via parallel LDG ----
    if (half == 0) {
        int i = t8;
        float xi = xval(i);
        int off = i * (i + 3) / 2;
        const float* __restrict__ rowp = g_Gp + off + 1;

        // 'a' contribution: R_i = -G(i,-1) = -g_Gp[off]
        float v = -__ldg(g_Gp + off);
        #pragma unroll
        for (int o = 16; o; o >>= 1) v += __shfl_xor_sync(0xffffffffu, v, o);
        if (lnl == 0) awt[wl] = v;

        int c = sC[i];
        float gv[CLEN];
        // state chain is pure ALU; all CLEN load addresses independent of loaded
        // data -> issued back-to-back, ~one L2 latency exposed total
        #pragma unroll
        for (int l = 0; l < CLEN; l++) {
            int cd = sc[l];
            if (cd == CODE_UP) {
                if (xi < sh[l]) c = i;
            } else if (cd != CODE_NONE) {
                c = min(c, cd);
            }
            gv[l] = __ldg(rowp + c);
        }
        #pragma unroll
        for (int l = 0; l < CLEN; l++) mat[l * NROW + i] = gv[l];
    }
    __syncthreads();

    // ---- epilogue over 16 warps: warp w reduces steps l = w, w+16 ----
    float asum = 0.0f;
    #pragma unroll
    for (int j = 0; j < 8; j++) asum += awt[j];
    float ainv = 1.0f / asum;

    for (int l = w; l < CLEN; l += 16) {
        int s = k * CLEN + l;
        const float* row = mat + l * NROW;
        float t = 0.0f;
        #pragma unroll
        for (int j = 0; j < 8; j++) t += row[ln + 32 * j];
        #pragma unroll
        for (int o = 16; o; o >>= 1) t += __shfl_xor_sync(0xffffffffu, t, o);
        if (ln == 0 && s >= 1 && s < S_STEPS) out[s - 1] = t * ainv;
    }
}

extern "C" void kernel_launch(void* const* d_in, const int* in_sizes, int n_in,
                              void* d_out, int out_size) {
    const float* hd  = (const float*)d_in[0];
    const float* raw = (const float*)d_in[1];
    if (n_in >= 2 && in_sizes[0] != M_STEPS) {
        const float* t = hd; hd = raw; raw = t;
    }
    float* out = (float*)d_out;

    kFused<<<NCHUNK, NTHR>>>(raw, hd, out);
}